// round 2
// baseline (speedup 1.0000x reference)
#include <cuda_runtime.h>
#include <cuda_bf16.h>
#include <math.h>

// Problem constants
// x: (32, 4096, 1024) f32 ; seeds: (32, 1024) ; proj_w: (1024, 32768) ; proj_b: (1024)
// out: (32, 1024) f32

#define Bb   32
#define Nn   4096
#define Dd   1024
#define Ss   32
#define Pp   1024
#define Ff   32768   // 32*1024

// Scratch (device globals; no allocations allowed)
__device__ float g_scores[(size_t)Bb * Ss * Nn];        // 16 MB, [b][s][n]
__device__ float g_flat[(size_t)Bb * Ff];               // 4 MB,  [b][s*1024+d]
__device__ float g_ppart[(size_t)4 * Bb * Ff];          // 16 MB, [ks][b][s][d]
__device__ float g_qpart[(size_t)64 * Bb * Pp];         // 8 MB,  [ks][b][p]

typedef unsigned long long ull;

__device__ __forceinline__ ull pkf(float x, float y) {
    ull r;
    asm("mov.b64 %0, {%1, %2};" : "=l"(r) : "f"(x), "f"(y));
    return r;
}
__device__ __forceinline__ void upk(ull v, float& x, float& y) {
    asm("mov.b64 {%0, %1}, %2;" : "=f"(x), "=f"(y) : "l"(v));
}
__device__ __forceinline__ void fma2(ull& d, ull a, ull b) {
    asm("fma.rn.f32x2 %0, %1, %2, %0;" : "+l"(d) : "l"(a), "l"(b));
}

// ---------------------------------------------------------------------------
// Unified GEMM core.
// Computes C[s][n] = scale * sum_k A[s][k]*B(k,n)
//   A: 32 rows (gmem row stride lda), contraction along columns.
//   B: TRANSB=true : B rows are OUTPUT n (512 rows, row stride ldb), contraction along cols.
//      TRANSB=false: B rows are CONTRACTION k, 512 output cols contiguous (row stride ldb).
//   C: 32 rows x 512 cols, row stride ldc.
// CTA: 256 threads. Per-thread: s in [8g, 8g+8), n in {4h..4h+3} U {256+4h..256+4h+3}.
// Accumulators are f32x2 pairs along n -> fma.rn.f32x2 (2x fp32 rate on sm_103a).
// ---------------------------------------------------------------------------
template <bool TRANSB>
__device__ __forceinline__ void gemm_core(
    const float* __restrict__ A, int lda,
    const float* __restrict__ B, int ldb,
    float* __restrict__ C, int ldc,
    int nchunks, float scale)
{
    extern __shared__ float smem[];
    float* As = smem;            // [k=32][s=32]
    float* Bs = smem + 1024;     // [k=32][n=512]

    const int t    = threadIdx.x;
    const int g    = t >> 6;     // 0..3  (s-group)
    const int h    = t & 63;     // 0..63 (n-group)
    const int lane = t & 31;
    const int w    = t >> 5;

    ull acc[8][4];
#pragma unroll
    for (int s = 0; s < 8; s++)
#pragma unroll
        for (int j = 0; j < 4; j++) acc[s][j] = 0ull;

    for (int ch = 0; ch < nchunks; ++ch) {
        __syncthreads();
        // ---- stage A tile (32 rows x 32 k), transposed to [k][s]
        {
            int s = t >> 3, q = t & 7;
            float4 v = *(const float4*)(A + (size_t)s * lda + ch * 32 + 4 * q);
            As[(4 * q + 0) * 32 + s] = v.x;
            As[(4 * q + 1) * 32 + s] = v.y;
            As[(4 * q + 2) * 32 + s] = v.z;
            As[(4 * q + 3) * 32 + s] = v.w;
        }
        // ---- stage B tile -> Bs[k][n]
        if (TRANSB) {
            const float* Bc = B + ch * 32;
#pragma unroll
            for (int rep = 0; rep < 2; ++rep) {
                int r = w * 64 + rep * 32 + lane;   // output-n row
                const float* src = Bc + (size_t)r * ldb;
                float4 v[8];
#pragma unroll
                for (int q = 0; q < 8; q++)
                    v[q] = *(const float4*)(src + 4 * q);
#pragma unroll
                for (int q = 0; q < 8; q++) {
                    Bs[(4 * q + 0) * 512 + r] = v[q].x;   // lanes -> consecutive n: conflict-free
                    Bs[(4 * q + 1) * 512 + r] = v[q].y;
                    Bs[(4 * q + 2) * 512 + r] = v[q].z;
                    Bs[(4 * q + 3) * 512 + r] = v[q].w;
                }
            }
        } else {
            const float* Bc = B + (size_t)(ch * 32) * ldb;
#pragma unroll
            for (int i = 0; i < 16; ++i) {
                int idx = t + 256 * i;
                int r = idx >> 7, cc = idx & 127;
                float4 v = *(const float4*)(Bc + (size_t)r * ldb + 4 * cc);
                *(float4*)&Bs[r * 512 + 4 * cc] = v;
            }
        }
        __syncthreads();
        // ---- compute 32 k-steps
#pragma unroll 4
        for (int k = 0; k < 32; ++k) {
            float4 a0 = *(const float4*)&As[k * 32 + 8 * g];
            float4 a1 = *(const float4*)&As[k * 32 + 8 * g + 4];
            ull A8[8];
            A8[0] = pkf(a0.x, a0.x); A8[1] = pkf(a0.y, a0.y);
            A8[2] = pkf(a0.z, a0.z); A8[3] = pkf(a0.w, a0.w);
            A8[4] = pkf(a1.x, a1.x); A8[5] = pkf(a1.y, a1.y);
            A8[6] = pkf(a1.z, a1.z); A8[7] = pkf(a1.w, a1.w);
            float4 b0 = *(const float4*)&Bs[k * 512 + 4 * h];
            float4 b1 = *(const float4*)&Bs[k * 512 + 256 + 4 * h];
            ull bb[4];
            bb[0] = pkf(b0.x, b0.y); bb[1] = pkf(b0.z, b0.w);
            bb[2] = pkf(b1.x, b1.y); bb[3] = pkf(b1.z, b1.w);
#pragma unroll
            for (int s = 0; s < 8; s++) {
#pragma unroll
                for (int j = 0; j < 4; j++) fma2(acc[s][j], A8[s], bb[j]);
            }
        }
    }
    // ---- epilogue
#pragma unroll
    for (int s = 0; s < 8; s++) {
        float* Crow = C + (size_t)(8 * g + s) * ldc;
#pragma unroll
        for (int j = 0; j < 4; j++) {
            float lo, hi;
            upk(acc[s][j], lo, hi);
            int col = (j < 2) ? (4 * h + 2 * j) : (256 + 4 * h + 2 * (j - 2));
            float2 o;
            o.x = lo * scale;
            o.y = hi * scale;
            *(float2*)&Crow[col] = o;
        }
    }
}

// ---------------------------------------------------------------------------
// K1: scores[b][s][n] = (1/32) * sum_d seeds[s][d] * x[b][n][d]
// grid (8 n-tiles, 32 b)
// ---------------------------------------------------------------------------
__global__ void __launch_bounds__(256, 2) k_scores(const float* __restrict__ x,
                                                   const float* __restrict__ seeds)
{
    int nt = blockIdx.x, b = blockIdx.y;
    gemm_core<true>(seeds, Dd,
                    x + (size_t)b * Nn * Dd + (size_t)nt * 512 * Dd, Dd,
                    g_scores + (size_t)b * Ss * Nn + nt * 512, Nn,
                    Dd / 32, 0.03125f);
}

// ---------------------------------------------------------------------------
// Softmax over n for each (b,s) row. grid 1024, 256 threads.
// ---------------------------------------------------------------------------
__global__ void k_softmax()
{
    __shared__ float red[256];
    const int t = threadIdx.x;
    float* row = g_scores + (size_t)blockIdx.x * Nn;
    float v[16];
    float m = -1e30f;
#pragma unroll
    for (int i = 0; i < 16; i++) {
        v[i] = row[t + 256 * i];
        m = fmaxf(m, v[i]);
    }
    red[t] = m;
    __syncthreads();
    for (int o = 128; o > 0; o >>= 1) {
        if (t < o) red[t] = fmaxf(red[t], red[t + o]);
        __syncthreads();
    }
    m = red[0];
    __syncthreads();
    float sum = 0.f;
#pragma unroll
    for (int i = 0; i < 16; i++) {
        v[i] = __expf(v[i] - m);
        sum += v[i];
    }
    red[t] = sum;
    __syncthreads();
    for (int o = 128; o > 0; o >>= 1) {
        if (t < o) red[t] += red[t + o];
        __syncthreads();
    }
    float inv = 1.0f / red[0];
#pragma unroll
    for (int i = 0; i < 16; i++) row[t + 256 * i] = v[i] * inv;
}

// ---------------------------------------------------------------------------
// K2: pooled partials. pooled[b][s][d] = sum_n attn[b][s][n] * x[b][n][d]
// split-K over n into 4 ranges of 1024. grid (4 ks, 2 d-tiles, 32 b)
// ---------------------------------------------------------------------------
__global__ void __launch_bounds__(256, 2) k_pool(const float* __restrict__ x)
{
    int ks = blockIdx.x, dt = blockIdx.y, b = blockIdx.z;
    gemm_core<false>(g_scores + (size_t)b * Ss * Nn + ks * 1024, Nn,
                     x + (size_t)b * Nn * Dd + (size_t)ks * 1024 * Dd + dt * 512, Dd,
                     g_ppart + (size_t)ks * Bb * Ff + (size_t)b * Ff + dt * 512, Dd,
                     1024 / 32, 1.0f);
}

// flat[b][f] = sum of 4 partials. grid 4096 x 256 covers 32*32768 = 1048576.
__global__ void k_flat()
{
    size_t i = (size_t)blockIdx.x * 256 + threadIdx.x;
    float s = g_ppart[i] + g_ppart[(size_t)1 * Bb * Ff + i]
            + g_ppart[(size_t)2 * Bb * Ff + i] + g_ppart[(size_t)3 * Bb * Ff + i];
    g_flat[i] = s;
}

// ---------------------------------------------------------------------------
// K3: projection partials. out[b][p] = sum_f flat[b][f] * W[p][f]
// split-K over f into 64 ranges of 512. grid (64 ks, 2 p-tiles)
// ---------------------------------------------------------------------------
__global__ void __launch_bounds__(256, 2) k_proj(const float* __restrict__ W)
{
    int ks = blockIdx.x, pt = blockIdx.y;
    gemm_core<true>(g_flat + ks * 512, Ff,
                    W + (size_t)pt * 512 * Ff + ks * 512, Ff,
                    g_qpart + (size_t)ks * Bb * Pp + pt * 512, Pp,
                    512 / 32, 1.0f);
}

// out[b][p] = bias[p] + sum_{ks<64} qpart. grid 128 x 256 covers 32768.
__global__ void k_out(const float* __restrict__ bias, float* __restrict__ out)
{
    int i = blockIdx.x * 256 + threadIdx.x;   // b*1024 + p
    int p = i & 1023;
    float s = bias[p];
#pragma unroll 8
    for (int ks = 0; ks < 64; ks++) s += g_qpart[(size_t)ks * Bb * Pp + i];
    out[i] = s;
}

// ---------------------------------------------------------------------------
extern "C" void kernel_launch(void* const* d_in, const int* in_sizes, int n_in,
                              void* d_out, int out_size)
{
    // Identify inputs by element count (robust to metadata ordering):
    //   x: 32*4096*1024 = 134217728 ; proj_w: 1024*32768 = 33554432
    //   seeds: 32*1024 = 32768      ; proj_b: 1024
    const float* x = nullptr; const float* seeds = nullptr;
    const float* W = nullptr; const float* bias = nullptr;
    for (int i = 0; i < n_in; i++) {
        switch (in_sizes[i]) {
            case 134217728: x     = (const float*)d_in[i]; break;
            case 33554432:  W     = (const float*)d_in[i]; break;
            case 32768:     seeds = (const float*)d_in[i]; break;
            case 1024:      bias  = (const float*)d_in[i]; break;
        }
    }
    float* out = (float*)d_out;

    const size_t smem = (1024 + 32 * 512) * sizeof(float);   // 69632 B
    cudaFuncSetAttribute(k_scores, cudaFuncAttributeMaxDynamicSharedMemorySize, (int)smem);
    cudaFuncSetAttribute(k_pool,   cudaFuncAttributeMaxDynamicSharedMemorySize, (int)smem);
    cudaFuncSetAttribute(k_proj,   cudaFuncAttributeMaxDynamicSharedMemorySize, (int)smem);

    k_scores<<<dim3(8, 32), 256, smem>>>(x, seeds);
    k_softmax<<<Bb * Ss, 256>>>();
    k_pool<<<dim3(4, 2, 32), 256, smem>>>(x);
    k_flat<<<(Bb * Ff) / 256, 256>>>();
    k_proj<<<dim3(64, 2), 256, smem>>>(W);
    k_out<<<(Bb * Pp) / 256, 256>>>(bias, out);
}